// round 2
// baseline (speedup 1.0000x reference)
#include <cuda_runtime.h>
#include <math.h>

// Problem constants
#define T_STEPS 32
#define BATCH   64
#define DIN     512
#define HID     512
#define VOCAB   32000
#define FFEAT   768
#define G3H     1536            // 3*HID
#define ROWS    (T_STEPS*BATCH) // 2048
#define BH      (BATCH*HID)     // 32768

// ---------------- scratch (static device globals; no allocs) ----------------
__device__ float g_Yemb [ROWS*DIN];
__device__ float g_GI   [ROWS*G3H];
__device__ float g_ct   [BH];
__device__ float g_GH   [BATCH*G3H];
__device__ float g_H    [(T_STEPS+1)*BH];   // slot 0 = h0 = 0
__device__ float g_X    [ROWS*HID];
__device__ float g_Q    [ROWS*HID];
__device__ float g_Kb   [ROWS*HID];
__device__ float g_V    [ROWS*HID];
__device__ float g_ATT  [ROWS*HID];
__device__ float g_H2   [ROWS*HID];
__device__ float g_LOGIT[ROWS*DIN];

// ---------------- generic SGEMM: C[M,N] = A[M,K] @ B[N,K]^T + bias (+tanh) ---
// Requires M%BM==0, N%BN==0, K%BK==0, and tile loads divisible as coded.
template<int BM,int BN,int BK,int TM,int TN,int ACT>
__global__ void sgemm_tn(const float* __restrict__ A, const float* __restrict__ B,
                         const float* __restrict__ bias, float* __restrict__ C,
                         int M, int N, int K)
{
    constexpr int THREADS = (BM/TM)*(BN/TN);
    constexpr int NTX = BN/TN;
    __shared__ float As[BK][BM+4];
    __shared__ float Bs[BK][BN+4];

    const int tid = threadIdx.x;
    const int m0 = blockIdx.y * BM;
    const int n0 = blockIdx.x * BN;
    const int tx = tid % NTX;
    const int ty = tid / NTX;

    float acc[TM][TN];
#pragma unroll
    for (int i = 0; i < TM; i++)
#pragma unroll
        for (int j = 0; j < TN; j++) acc[i][j] = 0.f;

    for (int k0 = 0; k0 < K; k0 += BK) {
        // load A tile (BM x BK) as float4, store transposed
        constexpr int A_IT = (BM*BK)/(THREADS*4);
#pragma unroll
        for (int it = 0; it < A_IT; it++) {
            int idx = (tid + it*THREADS) * 4;
            int r = idx / BK, c = idx % BK;
            float4 v = *(const float4*)&A[(size_t)(m0 + r)*K + k0 + c];
            As[c+0][r] = v.x; As[c+1][r] = v.y; As[c+2][r] = v.z; As[c+3][r] = v.w;
        }
        constexpr int B_IT = (BN*BK)/(THREADS*4);
#pragma unroll
        for (int it = 0; it < B_IT; it++) {
            int idx = (tid + it*THREADS) * 4;
            int r = idx / BK, c = idx % BK;
            float4 v = *(const float4*)&B[(size_t)(n0 + r)*K + k0 + c];
            Bs[c+0][r] = v.x; Bs[c+1][r] = v.y; Bs[c+2][r] = v.z; Bs[c+3][r] = v.w;
        }
        __syncthreads();

#pragma unroll
        for (int kk = 0; kk < BK; kk++) {
            float ra[TM], rb[TN];
            if constexpr (TM == 8) {
                *(float4*)&ra[0] = *(const float4*)&As[kk][ty*TM];
                *(float4*)&ra[4] = *(const float4*)&As[kk][ty*TM+4];
            } else if constexpr (TM == 4) {
                *(float4*)&ra[0] = *(const float4*)&As[kk][ty*TM];
            } else {
                *(float2*)&ra[0] = *(const float2*)&As[kk][ty*TM];
            }
            if constexpr (TN == 8) {
                *(float4*)&rb[0] = *(const float4*)&Bs[kk][tx*TN];
                *(float4*)&rb[4] = *(const float4*)&Bs[kk][tx*TN+4];
            } else {
                *(float4*)&rb[0] = *(const float4*)&Bs[kk][tx*TN];
            }
#pragma unroll
            for (int i = 0; i < TM; i++)
#pragma unroll
                for (int j = 0; j < TN; j++)
                    acc[i][j] = fmaf(ra[i], rb[j], acc[i][j]);
        }
        __syncthreads();
    }

    // epilogue: bias (+tanh), vectorized stores
#pragma unroll
    for (int i = 0; i < TM; i++) {
        int m = m0 + ty*TM + i;
        float* crow = C + (size_t)m * N + n0 + tx*TN;
#pragma unroll
        for (int j4 = 0; j4 < TN; j4 += 4) {
            float4 v;
            float b0 = bias[n0 + tx*TN + j4 + 0];
            float b1 = bias[n0 + tx*TN + j4 + 1];
            float b2 = bias[n0 + tx*TN + j4 + 2];
            float b3 = bias[n0 + tx*TN + j4 + 3];
            v.x = acc[i][j4+0] + b0;
            v.y = acc[i][j4+1] + b1;
            v.z = acc[i][j4+2] + b2;
            v.w = acc[i][j4+3] + b3;
            if constexpr (ACT == 1) {
                v.x = tanhf(v.x); v.y = tanhf(v.y); v.z = tanhf(v.z); v.w = tanhf(v.w);
            }
            *(float4*)&crow[j4] = v;
        }
    }
}

// ---------------- small kernels ----------------
__global__ void zero_kernel(float* __restrict__ p, int n) {
    int i = blockIdx.x * blockDim.x + threadIdx.x;
    if (i < n) p[i] = 0.f;
}

// gather embedding rows: Yemb[i,:] = emb[y[i],:]
__global__ void gather_emb(const int* __restrict__ y, const float* __restrict__ emb,
                           float* __restrict__ Yemb)
{
    int row = blockIdx.x;              // 0..ROWS-1 (= t*B + b, matches y layout [T,B])
    int r = y[row];
    const float4* src = (const float4*)(emb + (size_t)r * DIN);
    float4* dst = (float4*)(Yemb + (size_t)row * DIN);
    for (int j = threadIdx.x; j < DIN/4; j += blockDim.x) dst[j] = src[j];
}

__device__ __forceinline__ float sigmoidf_(float x) { return 1.f / (1.f + __expf(-x)); }

// GRU gates: torch order (r, z, n)
__global__ void gru_gate(const float* __restrict__ GIt, const float* __restrict__ GH,
                         const float* __restrict__ Hprev, float* __restrict__ Hnext)
{
    int idx = blockIdx.x * blockDim.x + threadIdx.x;  // 0..BH-1
    int b = idx >> 9;        // /512
    int j = idx & 511;
    const float* gi = GIt + (size_t)b * G3H;
    const float* gh = GH  + (size_t)b * G3H;
    float r = sigmoidf_(gi[j]        + gh[j]);
    float z = sigmoidf_(gi[HID + j]  + gh[HID + j]);
    float n = tanhf    (gi[2*HID + j] + r * gh[2*HID + j]);
    float h = Hprev[idx];
    Hnext[idx] = (1.f - z) * n + z * h;
}

// X[t*B+b, :] = h1[t][b,:] * ct[b,:]
__global__ void mul_ct(const float* __restrict__ H, const float* __restrict__ ct,
                       float* __restrict__ X)
{
    int i = blockIdx.x * blockDim.x + threadIdx.x;   // 0..ROWS*HID-1
    X[i] = H[i + BH] * ct[i & (BH - 1)];
}

// per-(t,b) 8-head self-attention on a single vector (heads act as sequence)
__global__ void attn_kernel(const float* __restrict__ Q, const float* __restrict__ K,
                            const float* __restrict__ V, float* __restrict__ O)
{
    int row = blockIdx.x;   // 0..ROWS-1
    int tid = threadIdx.x;  // 64 threads
    __shared__ float q[512], k[512], v[512], sc[64], w[64];
    const float* qr = Q + (size_t)row * HID;
    const float* kr = K + (size_t)row * HID;
    const float* vr = V + (size_t)row * HID;
    for (int i = tid; i < HID; i += 64) { q[i] = qr[i]; k[i] = kr[i]; v[i] = vr[i]; }
    __syncthreads();
    {
        int h = tid >> 3, g = tid & 7;
        float s = 0.f;
#pragma unroll
        for (int d = 0; d < 64; d++) s = fmaf(q[h*64+d], k[g*64+d], s);
        sc[tid] = s * (1.f / 64.f);   // note: /head_dim, not sqrt
    }
    __syncthreads();
    if (tid < 8) {
        float m = -1e30f;
#pragma unroll
        for (int g = 0; g < 8; g++) m = fmaxf(m, sc[tid*8+g]);
        float e[8], s = 0.f;
#pragma unroll
        for (int g = 0; g < 8; g++) { e[g] = __expf(sc[tid*8+g] - m); s += e[g]; }
        float inv = 1.f / s;
#pragma unroll
        for (int g = 0; g < 8; g++) w[tid*8+g] = e[g] * inv;
    }
    __syncthreads();
    {
        int h = tid >> 3, d0 = (tid & 7) * 8;
        float o[8];
#pragma unroll
        for (int d = 0; d < 8; d++) o[d] = 0.f;
#pragma unroll
        for (int g = 0; g < 8; g++) {
            float wg = w[h*8+g];
#pragma unroll
            for (int d = 0; d < 8; d++) o[d] = fmaf(wg, v[g*64 + d0 + d], o[d]);
        }
        float* orow = O + (size_t)row * HID + h*64 + d0;
#pragma unroll
        for (int d = 0; d < 8; d++) orow[d] = o[d];
    }
}

// row softmax over VOCAB, in place on d_out. One block per row.
__global__ void softmax_rows(float* __restrict__ C)
{
    float* row = C + (size_t)blockIdx.x * VOCAB;
    int tid = threadIdx.x;
    __shared__ float red[256];
    float m = -1e30f;
    for (int j = tid; j < VOCAB; j += 256) m = fmaxf(m, row[j]);
    red[tid] = m; __syncthreads();
    for (int s = 128; s > 0; s >>= 1) { if (tid < s) red[tid] = fmaxf(red[tid], red[tid+s]); __syncthreads(); }
    m = red[0]; __syncthreads();
    float s = 0.f;
    for (int j = tid; j < VOCAB; j += 256) s += __expf(row[j] - m);
    red[tid] = s; __syncthreads();
    for (int st = 128; st > 0; st >>= 1) { if (tid < st) red[tid] += red[tid+st]; __syncthreads(); }
    float inv = 1.f / red[0];
    __syncthreads();
    for (int j = tid; j < VOCAB; j += 256) row[j] = __expf(row[j] - m) * inv;
}

// ---------------- launch ----------------
extern "C" void kernel_launch(void* const* d_in, const int* in_sizes, int n_in,
                              void* d_out, int out_size)
{
    const int*   y     = (const int*)  d_in[0];
    const float* ctx   = (const float*)d_in[1];   // [1,B,FFEAT] -> [B,FFEAT]
    const float* emb   = (const float*)d_in[2];
    const float* W_ih  = (const float*)d_in[3];
    const float* b_ih  = (const float*)d_in[4];
    const float* W_hh  = (const float*)d_in[5];
    const float* b_hh  = (const float*)d_in[6];
    const float* W_att = (const float*)d_in[7];
    const float* b_att = (const float*)d_in[8];
    const float* Wq    = (const float*)d_in[9];
    const float* bq    = (const float*)d_in[10];
    const float* Wk    = (const float*)d_in[11];
    const float* bk    = (const float*)d_in[12];
    const float* Wv    = (const float*)d_in[13];
    const float* bv    = (const float*)d_in[14];
    const float* Wfc   = (const float*)d_in[15];
    const float* bfc   = (const float*)d_in[16];
    const float* W_h2o = (const float*)d_in[17];
    const float* b_h2o = (const float*)d_in[18];
    const float* W_out = (const float*)d_in[19];
    const float* b_out = (const float*)d_in[20];
    float* out = (float*)d_out;

    float *pYemb, *pGI, *pct, *pGH, *pH, *pX, *pQ, *pK, *pV, *pATT, *pH2, *pLOGIT;
    cudaGetSymbolAddress((void**)&pYemb,  g_Yemb);
    cudaGetSymbolAddress((void**)&pGI,    g_GI);
    cudaGetSymbolAddress((void**)&pct,    g_ct);
    cudaGetSymbolAddress((void**)&pGH,    g_GH);
    cudaGetSymbolAddress((void**)&pH,     g_H);
    cudaGetSymbolAddress((void**)&pX,     g_X);
    cudaGetSymbolAddress((void**)&pQ,     g_Q);
    cudaGetSymbolAddress((void**)&pK,     g_Kb);
    cudaGetSymbolAddress((void**)&pV,     g_V);
    cudaGetSymbolAddress((void**)&pATT,   g_ATT);
    cudaGetSymbolAddress((void**)&pH2,    g_H2);
    cudaGetSymbolAddress((void**)&pLOGIT, g_LOGIT);

    // h0 = 0
    zero_kernel<<<BH/256, 256>>>(pH, BH);

    // embedding gather for all (t,b)
    gather_emb<<<ROWS, 128>>>(y, emb, pYemb);

    // ct = tanh(ctx @ W_att^T + b_att)   [64,512], K=768
    {
        dim3 grid(HID/64, BATCH/64);
        sgemm_tn<64,64,16,4,4,1><<<grid, 256>>>(ctx, W_att, b_att, pct, BATCH, HID, FFEAT);
    }

    // GI = Yemb @ W_ih^T + b_ih          [2048,1536], K=512
    {
        dim3 grid(G3H/64, ROWS/64);
        sgemm_tn<64,64,16,4,4,0><<<grid, 256>>>(pYemb, W_ih, b_ih, pGI, ROWS, G3H, DIN);
    }

    // sequential GRU scan
    for (int t = 0; t < T_STEPS; t++) {
        dim3 grid(G3H/64, BATCH/16);   // (24,4) = 96 CTAs
        sgemm_tn<16,64,32,2,4,0><<<grid, 128>>>(pH + (size_t)t*BH, W_hh, b_hh, pGH,
                                                BATCH, G3H, HID);
        gru_gate<<<BH/256, 256>>>(pGI + (size_t)t*BATCH*G3H, pGH,
                                  pH + (size_t)t*BH, pH + (size_t)(t+1)*BH);
    }

    // X = h1 * ct  (all t)
    mul_ct<<<(ROWS*HID)/256, 256>>>(pH, pct, pX);

    // Q/K/V projections  [2048,512], K=512
    {
        dim3 grid(HID/64, ROWS/64);
        sgemm_tn<64,64,16,4,4,0><<<grid, 256>>>(pX, Wq, bq, pQ, ROWS, HID, HID);
        sgemm_tn<64,64,16,4,4,0><<<grid, 256>>>(pX, Wk, bk, pK, ROWS, HID, HID);
        sgemm_tn<64,64,16,4,4,0><<<grid, 256>>>(pX, Wv, bv, pV, ROWS, HID, HID);
    }

    // attention per (t,b)
    attn_kernel<<<ROWS, 64>>>(pQ, pK, pV, pATT);

    // h2 = att @ Wfc^T + bfc
    {
        dim3 grid(HID/64, ROWS/64);
        sgemm_tn<64,64,16,4,4,0><<<grid, 256>>>(pATT, Wfc, bfc, pH2, ROWS, HID, HID);
    }

    // logit = tanh(h2 @ W_h2o^T + b_h2o)
    {
        dim3 grid(DIN/64, ROWS/64);
        sgemm_tn<64,64,16,4,4,1><<<grid, 256>>>(pH2, W_h2o, b_h2o, pLOGIT, ROWS, DIN, HID);
    }

    // scores = logit @ W_out^T + b_out  -> d_out   [2048, 32000], K=512
    {
        dim3 grid(VOCAB/128, ROWS/128);   // (250,16)
        sgemm_tn<128,128,16,8,8,0><<<grid, 256>>>(pLOGIT, W_out, b_out, out, ROWS, VOCAB, DIN);
    }

    // softmax rows in place
    softmax_rows<<<ROWS, 256>>>(out);
}

// round 5
// speedup vs baseline: 1.4321x; 1.4321x over previous
#include <cuda_runtime.h>
#include <math.h>

// Problem constants
#define T_STEPS 32
#define BATCH   64
#define DIN     512
#define HID     512
#define VOCAB   32000
#define FFEAT   768
#define G3H     1536            // 3*HID
#define ROWS    (T_STEPS*BATCH) // 2048
#define BH      (BATCH*HID)     // 32768

// ---------------- scratch (static device globals; no allocs) ----------------
__device__ float g_Yemb [ROWS*DIN];
__device__ float g_GI   [ROWS*G3H];
__device__ float g_ct   [BH];
__device__ float g_GH   [BATCH*G3H];
__device__ float g_H    [(T_STEPS+1)*BH];   // slot 0 = h0 = 0
__device__ float g_X    [ROWS*HID];
__device__ float g_Q    [ROWS*HID];
__device__ float g_Kb   [ROWS*HID];
__device__ float g_V    [ROWS*HID];
__device__ float g_ATT  [ROWS*HID];
__device__ float g_H2   [ROWS*HID];
__device__ float g_LOGIT[ROWS*DIN];

// ---------------- generic SGEMM: C[M,N] = A[M,K] @ B[N,K]^T + bias (+tanh) ---
template<int BM,int BN,int BK,int TM,int TN,int ACT>
__global__ void sgemm_tn(const float* __restrict__ A, const float* __restrict__ B,
                         const float* __restrict__ bias, float* __restrict__ C,
                         int M, int N, int K)
{
    constexpr int THREADS = (BM/TM)*(BN/TN);
    constexpr int NTX = BN/TN;
    __shared__ float As[BK][BM+4];
    __shared__ float Bs[BK][BN+4];

    const int tid = threadIdx.x;
    const int m0 = blockIdx.y * BM;
    const int n0 = blockIdx.x * BN;
    const int tx = tid % NTX;
    const int ty = tid / NTX;

    float acc[TM][TN];
#pragma unroll
    for (int i = 0; i < TM; i++)
#pragma unroll
        for (int j = 0; j < TN; j++) acc[i][j] = 0.f;

    for (int k0 = 0; k0 < K; k0 += BK) {
        constexpr int A_IT = (BM*BK)/(THREADS*4);
#pragma unroll
        for (int it = 0; it < A_IT; it++) {
            int idx = (tid + it*THREADS) * 4;
            int r = idx / BK, c = idx % BK;
            float4 v = *(const float4*)&A[(size_t)(m0 + r)*K + k0 + c];
            As[c+0][r] = v.x; As[c+1][r] = v.y; As[c+2][r] = v.z; As[c+3][r] = v.w;
        }
        constexpr int B_IT = (BN*BK)/(THREADS*4);
#pragma unroll
        for (int it = 0; it < B_IT; it++) {
            int idx = (tid + it*THREADS) * 4;
            int r = idx / BK, c = idx % BK;
            float4 v = *(const float4*)&B[(size_t)(n0 + r)*K + k0 + c];
            Bs[c+0][r] = v.x; Bs[c+1][r] = v.y; Bs[c+2][r] = v.z; Bs[c+3][r] = v.w;
        }
        __syncthreads();

#pragma unroll
        for (int kk = 0; kk < BK; kk++) {
            float ra[TM], rb[TN];
            if constexpr (TM == 4) {
                *(float4*)&ra[0] = *(const float4*)&As[kk][ty*TM];
            } else {
                *(float2*)&ra[0] = *(const float2*)&As[kk][ty*TM];
            }
            *(float4*)&rb[0] = *(const float4*)&Bs[kk][tx*TN];
#pragma unroll
            for (int i = 0; i < TM; i++)
#pragma unroll
                for (int j = 0; j < TN; j++)
                    acc[i][j] = fmaf(ra[i], rb[j], acc[i][j]);
        }
        __syncthreads();
    }

#pragma unroll
    for (int i = 0; i < TM; i++) {
        int m = m0 + ty*TM + i;
        float* crow = C + (size_t)m * N + n0 + tx*TN;
#pragma unroll
        for (int j4 = 0; j4 < TN; j4 += 4) {
            float4 v;
            v.x = acc[i][j4+0] + bias[n0 + tx*TN + j4 + 0];
            v.y = acc[i][j4+1] + bias[n0 + tx*TN + j4 + 1];
            v.z = acc[i][j4+2] + bias[n0 + tx*TN + j4 + 2];
            v.w = acc[i][j4+3] + bias[n0 + tx*TN + j4 + 3];
            if constexpr (ACT == 1) {
                v.x = tanhf(v.x); v.y = tanhf(v.y); v.z = tanhf(v.z); v.w = tanhf(v.w);
            }
            *(float4*)&crow[j4] = v;
        }
    }
}

// ---------------- tf32 tensor-core GEMM for the output projection -----------
// C[M,N] = A[M,K] @ B[N,K]^T + bias.  M%128==0, N%128==0, K%32==0.
// CTA tile 128x128x32, 8 warps (2 in M x 4 in N), warp tile 64x32.
// mma.sync.m16n8k8 tf32, fp32 accumulate. smem row stride 36 -> bank = 4g+c
// for fragment loads (conflict-free).
#define OSTR 36

__device__ __forceinline__ unsigned f2tf32(float x) {
    unsigned r;
    asm("cvt.rna.tf32.f32 %0, %1;" : "=r"(r) : "f"(x));
    return r;
}

__device__ __forceinline__ void mma_tf32(float* d, const unsigned* a, const unsigned* b) {
    asm volatile(
        "mma.sync.aligned.m16n8k8.row.col.f32.tf32.tf32.f32 "
        "{%0,%1,%2,%3}, {%4,%5,%6,%7}, {%8,%9}, {%0,%1,%2,%3};\n"
        : "+f"(d[0]), "+f"(d[1]), "+f"(d[2]), "+f"(d[3])
        : "r"(a[0]), "r"(a[1]), "r"(a[2]), "r"(a[3]),
          "r"(b[0]), "r"(b[1]));
}

__global__ __launch_bounds__(256, 1)
void gemm_tf32_bias(const float* __restrict__ A, const float* __restrict__ B,
                    const float* __restrict__ bias, float* __restrict__ C,
                    int M, int N, int K)
{
    __shared__ unsigned As[128*OSTR];
    __shared__ unsigned Bs[128*OSTR];

    const int tid  = threadIdx.x;
    const int warp = tid >> 5;
    const int lane = tid & 31;
    const int g    = lane >> 2;      // groupID 0..7
    const int c    = lane & 3;       // threadID_in_group 0..3
    const int wm   = warp & 1;       // warp row 0..1  (64 rows each)
    const int wn   = warp >> 1;      // warp col 0..3  (32 cols each)
    const int m0   = blockIdx.y * 128;
    const int n0   = blockIdx.x * 128;

    float acc[4][4][4];
#pragma unroll
    for (int mi = 0; mi < 4; mi++)
#pragma unroll
        for (int ni = 0; ni < 4; ni++)
#pragma unroll
            for (int r = 0; r < 4; r++) acc[mi][ni][r] = 0.f;

    for (int k0 = 0; k0 < K; k0 += 32) {
        // load + convert A tile (128 x 32) and B tile (128 x 32)
#pragma unroll
        for (int it = 0; it < 4; it++) {
            int idx = tid + it*256;          // 0..1023 float4 slots
            int r  = idx >> 3;               // row 0..127
            int cc = (idx & 7) * 4;          // col 0,4,..,28
            float4 va = *(const float4*)&A[(size_t)(m0 + r)*K + k0 + cc];
            unsigned* da = &As[r*OSTR + cc];
            da[0] = f2tf32(va.x); da[1] = f2tf32(va.y);
            da[2] = f2tf32(va.z); da[3] = f2tf32(va.w);
            float4 vb = *(const float4*)&B[(size_t)(n0 + r)*K + k0 + cc];
            unsigned* db = &Bs[r*OSTR + cc];
            db[0] = f2tf32(vb.x); db[1] = f2tf32(vb.y);
            db[2] = f2tf32(vb.z); db[3] = f2tf32(vb.w);
        }
        __syncthreads();

#pragma unroll
        for (int ks = 0; ks < 32; ks += 8) {
            unsigned af[4][4], bf[4][2];
#pragma unroll
            for (int mi = 0; mi < 4; mi++) {
                int rb = wm*64 + mi*16;
                af[mi][0] = As[(rb + g    )*OSTR + ks + c    ];
                af[mi][1] = As[(rb + g + 8)*OSTR + ks + c    ];
                af[mi][2] = As[(rb + g    )*OSTR + ks + c + 4];
                af[mi][3] = As[(rb + g + 8)*OSTR + ks + c + 4];
            }
#pragma unroll
            for (int ni = 0; ni < 4; ni++) {
                int nb = wn*32 + ni*8;
                bf[ni][0] = Bs[(nb + g)*OSTR + ks + c    ];
                bf[ni][1] = Bs[(nb + g)*OSTR + ks + c + 4];
            }
#pragma unroll
            for (int mi = 0; mi < 4; mi++)
#pragma unroll
                for (int ni = 0; ni < 4; ni++)
                    mma_tf32(acc[mi][ni], af[mi], bf[ni]);
        }
        __syncthreads();
    }

    // epilogue: bias + store (float2 per 8-wide tile row)
#pragma unroll
    for (int mi = 0; mi < 4; mi++) {
        int row = m0 + wm*64 + mi*16 + g;
#pragma unroll
        for (int ni = 0; ni < 4; ni++) {
            int col = n0 + wn*32 + ni*8 + c*2;
            float b0 = bias[col], b1 = bias[col+1];
            float2 v0 = make_float2(acc[mi][ni][0] + b0, acc[mi][ni][1] + b1);
            float2 v1 = make_float2(acc[mi][ni][2] + b0, acc[mi][ni][3] + b1);
            *(float2*)&C[(size_t)row      * N + col] = v0;
            *(float2*)&C[(size_t)(row + 8)* N + col] = v1;
        }
    }
}

// ---------------- small kernels ----------------
__global__ void zero_kernel(float* __restrict__ p, int n) {
    int i = blockIdx.x * blockDim.x + threadIdx.x;
    if (i < n) p[i] = 0.f;
}

__global__ void gather_emb(const int* __restrict__ y, const float* __restrict__ emb,
                           float* __restrict__ Yemb)
{
    int row = blockIdx.x;
    int r = y[row];
    const float4* src = (const float4*)(emb + (size_t)r * DIN);
    float4* dst = (float4*)(Yemb + (size_t)row * DIN);
    for (int j = threadIdx.x; j < DIN/4; j += blockDim.x) dst[j] = src[j];
}

__device__ __forceinline__ float sigmoidf_(float x) { return 1.f / (1.f + __expf(-x)); }

__global__ void gru_gate(const float* __restrict__ GIt, const float* __restrict__ GH,
                         const float* __restrict__ Hprev, float* __restrict__ Hnext)
{
    int idx = blockIdx.x * blockDim.x + threadIdx.x;
    int b = idx >> 9;
    int j = idx & 511;
    const float* gi = GIt + (size_t)b * G3H;
    const float* gh = GH  + (size_t)b * G3H;
    float r = sigmoidf_(gi[j]        + gh[j]);
    float z = sigmoidf_(gi[HID + j]  + gh[HID + j]);
    float n = tanhf    (gi[2*HID + j] + r * gh[2*HID + j]);
    float h = Hprev[idx];
    Hnext[idx] = (1.f - z) * n + z * h;
}

__global__ void mul_ct(const float* __restrict__ H, const float* __restrict__ ct,
                       float* __restrict__ X)
{
    int i = blockIdx.x * blockDim.x + threadIdx.x;
    X[i] = H[i + BH] * ct[i & (BH - 1)];
}

__global__ void attn_kernel(const float* __restrict__ Q, const float* __restrict__ K,
                            const float* __restrict__ V, float* __restrict__ O)
{
    int row = blockIdx.x;
    int tid = threadIdx.x;
    __shared__ float q[512], k[512], v[512], sc[64], w[64];
    const float* qr = Q + (size_t)row * HID;
    const float* kr = K + (size_t)row * HID;
    const float* vr = V + (size_t)row * HID;
    for (int i = tid; i < HID; i += 64) { q[i] = qr[i]; k[i] = kr[i]; v[i] = vr[i]; }
    __syncthreads();
    {
        int h = tid >> 3, gg = tid & 7;
        float s = 0.f;
#pragma unroll
        for (int d = 0; d < 64; d++) s = fmaf(q[h*64+d], k[gg*64+d], s);
        sc[tid] = s * (1.f / 64.f);
    }
    __syncthreads();
    if (tid < 8) {
        float m = -1e30f;
#pragma unroll
        for (int gg = 0; gg < 8; gg++) m = fmaxf(m, sc[tid*8+gg]);
        float e[8], s = 0.f;
#pragma unroll
        for (int gg = 0; gg < 8; gg++) { e[gg] = __expf(sc[tid*8+gg] - m); s += e[gg]; }
        float inv = 1.f / s;
#pragma unroll
        for (int gg = 0; gg < 8; gg++) w[tid*8+gg] = e[gg] * inv;
    }
    __syncthreads();
    {
        int h = tid >> 3, d0 = (tid & 7) * 8;
        float o[8];
#pragma unroll
        for (int d = 0; d < 8; d++) o[d] = 0.f;
#pragma unroll
        for (int gg = 0; gg < 8; gg++) {
            float wg = w[h*8+gg];
#pragma unroll
            for (int d = 0; d < 8; d++) o[d] = fmaf(wg, v[gg*64 + d0 + d], o[d]);
        }
        float* orow = O + (size_t)row * HID + h*64 + d0;
#pragma unroll
        for (int d = 0; d < 8; d++) orow[d] = o[d];
    }
}

__global__ void softmax_rows(float* __restrict__ C)
{
    float* row = C + (size_t)blockIdx.x * VOCAB;
    int tid = threadIdx.x;
    __shared__ float red[256];
    float m = -1e30f;
    for (int j = tid; j < VOCAB; j += 256) m = fmaxf(m, row[j]);
    red[tid] = m; __syncthreads();
    for (int s = 128; s > 0; s >>= 1) { if (tid < s) red[tid] = fmaxf(red[tid], red[tid+s]); __syncthreads(); }
    m = red[0]; __syncthreads();
    float s = 0.f;
    for (int j = tid; j < VOCAB; j += 256) s += __expf(row[j] - m);
    red[tid] = s; __syncthreads();
    for (int st = 128; st > 0; st >>= 1) { if (tid < st) red[tid] += red[tid+st]; __syncthreads(); }
    float inv = 1.f / red[0];
    __syncthreads();
    for (int j = tid; j < VOCAB; j += 256) row[j] = __expf(row[j] - m) * inv;
}

// ---------------- launch ----------------
extern "C" void kernel_launch(void* const* d_in, const int* in_sizes, int n_in,
                              void* d_out, int out_size)
{
    const int*   y     = (const int*)  d_in[0];
    const float* ctx   = (const float*)d_in[1];
    const float* emb   = (const float*)d_in[2];
    const float* W_ih  = (const float*)d_in[3];
    const float* b_ih  = (const float*)d_in[4];
    const float* W_hh  = (const float*)d_in[5];
    const float* b_hh  = (const float*)d_in[6];
    const float* W_att = (const float*)d_in[7];
    const float* b_att = (const float*)d_in[8];
    const float* Wq    = (const float*)d_in[9];
    const float* bq    = (const float*)d_in[10];
    const float* Wk    = (const float*)d_in[11];
    const float* bk    = (const float*)d_in[12];
    const float* Wv    = (const float*)d_in[13];
    const float* bv    = (const float*)d_in[14];
    const float* Wfc   = (const float*)d_in[15];
    const float* bfc   = (const float*)d_in[16];
    const float* W_h2o = (const float*)d_in[17];
    const float* b_h2o = (const float*)d_in[18];
    const float* W_out = (const float*)d_in[19];
    const float* b_out = (const float*)d_in[20];
    float* out = (float*)d_out;

    float *pYemb, *pGI, *pct, *pGH, *pH, *pX, *pQ, *pK, *pV, *pATT, *pH2, *pLOGIT;
    cudaGetSymbolAddress((void**)&pYemb,  g_Yemb);
    cudaGetSymbolAddress((void**)&pGI,    g_GI);
    cudaGetSymbolAddress((void**)&pct,    g_ct);
    cudaGetSymbolAddress((void**)&pGH,    g_GH);
    cudaGetSymbolAddress((void**)&pH,     g_H);
    cudaGetSymbolAddress((void**)&pX,     g_X);
    cudaGetSymbolAddress((void**)&pQ,     g_Q);
    cudaGetSymbolAddress((void**)&pK,     g_Kb);
    cudaGetSymbolAddress((void**)&pV,     g_V);
    cudaGetSymbolAddress((void**)&pATT,   g_ATT);
    cudaGetSymbolAddress((void**)&pH2,    g_H2);
    cudaGetSymbolAddress((void**)&pLOGIT, g_LOGIT);

    zero_kernel<<<BH/256, 256>>>(pH, BH);
    gather_emb<<<ROWS, 128>>>(y, emb, pYemb);

    // ct = tanh(ctx @ W_att^T + b_att)
    {
        dim3 grid(HID/64, BATCH/64);
        sgemm_tn<64,64,16,4,4,1><<<grid, 256>>>(ctx, W_att, b_att, pct, BATCH, HID, FFEAT);
    }

    // GI = Yemb @ W_ih^T + b_ih
    {
        dim3 grid(G3H/64, ROWS/64);
        sgemm_tn<64,64,16,4,4,0><<<grid, 256>>>(pYemb, W_ih, b_ih, pGI, ROWS, G3H, DIN);
    }

    // sequential GRU scan
    for (int t = 0; t < T_STEPS; t++) {
        dim3 grid(G3H/64, BATCH/16);
        sgemm_tn<16,64,32,2,4,0><<<grid, 128>>>(pH + (size_t)t*BH, W_hh, b_hh, pGH,
                                                BATCH, G3H, HID);
        gru_gate<<<BH/256, 256>>>(pGI + (size_t)t*BATCH*G3H, pGH,
                                  pH + (size_t)t*BH, pH + (size_t)(t+1)*BH);
    }

    mul_ct<<<(ROWS*HID)/256, 256>>>(pH, pct, pX);

    // Q/K/V projections
    {
        dim3 grid(HID/64, ROWS/64);
        sgemm_tn<64,64,16,4,4,0><<<grid, 256>>>(pX, Wq, bq, pQ, ROWS, HID, HID);
        sgemm_tn<64,64,16,4,4,0><<<grid, 256>>>(pX, Wk, bk, pK, ROWS, HID, HID);
        sgemm_tn<64,64,16,4,4,0><<<grid, 256>>>(pX, Wv, bv, pV, ROWS, HID, HID);
    }

    attn_kernel<<<ROWS, 64>>>(pQ, pK, pV, pATT);

    // h2 = att @ Wfc^T + bfc
    {
        dim3 grid(HID/64, ROWS/64);
        sgemm_tn<64,64,16,4,4,0><<<grid, 256>>>(pATT, Wfc, bfc, pH2, ROWS, HID, HID);
    }

    // logit = tanh(h2 @ W_h2o^T + b_h2o)
    {
        dim3 grid(DIN/64, ROWS/64);
        sgemm_tn<64,64,16,4,4,1><<<grid, 256>>>(pH2, W_h2o, b_h2o, pLOGIT, ROWS, DIN, HID);
    }

    // scores = logit @ W_out^T + b_out  (tf32 tensor cores)
    {
        dim3 grid(VOCAB/128, ROWS/128);   // (250, 16)
        gemm_tf32_bias<<<grid, 256>>>(pLOGIT, W_out, b_out, out, ROWS, VOCAB, DIN);
    }

    softmax_rows<<<ROWS, 256>>>(out);
}

// round 6
// speedup vs baseline: 1.7898x; 1.2497x over previous
#include <cuda_runtime.h>
#include <cuda_bf16.h>
#include <math.h>

// Problem constants
#define T_STEPS 32
#define BATCH   64
#define DIN     512
#define HID     512
#define VOCAB   32000
#define FFEAT   768
#define G3H     1536            // 3*HID
#define ROWS    (T_STEPS*BATCH) // 2048
#define BH      (BATCH*HID)     // 32768

// ---------------- scratch (static device globals; no allocs) ----------------
__device__ float g_Yemb [ROWS*DIN];
__device__ float g_GI   [ROWS*G3H];
__device__ float g_ct   [BH];
__device__ float g_GH   [BATCH*G3H];
__device__ float g_H    [(T_STEPS+1)*BH];   // slot 0 = h0 = 0
__device__ float g_X    [ROWS*HID];
__device__ float g_Q    [ROWS*HID];
__device__ float g_Kb   [ROWS*HID];
__device__ float g_V    [ROWS*HID];
__device__ float g_ATT  [ROWS*HID];
__device__ float g_H2   [ROWS*HID];
__device__ float g_LOGIT[ROWS*DIN];
__device__ __nv_bfloat16 g_LOGIT_BF[ROWS*DIN];
__device__ __nv_bfloat16 g_WOUT_BF [VOCAB*DIN];

// ---------------- generic SGEMM: C[M,N] = A[M,K] @ B[N,K]^T + bias (+tanh) ---
template<int BM,int BN,int BK,int TM,int TN,int ACT>
__global__ void sgemm_tn(const float* __restrict__ A, const float* __restrict__ B,
                         const float* __restrict__ bias, float* __restrict__ C,
                         int M, int N, int K)
{
    constexpr int THREADS = (BM/TM)*(BN/TN);
    constexpr int NTX = BN/TN;
    __shared__ float As[BK][BM+4];
    __shared__ float Bs[BK][BN+4];

    const int tid = threadIdx.x;
    const int m0 = blockIdx.y * BM;
    const int n0 = blockIdx.x * BN;
    const int tx = tid % NTX;
    const int ty = tid / NTX;

    float acc[TM][TN];
#pragma unroll
    for (int i = 0; i < TM; i++)
#pragma unroll
        for (int j = 0; j < TN; j++) acc[i][j] = 0.f;

    for (int k0 = 0; k0 < K; k0 += BK) {
        constexpr int A_IT = (BM*BK)/(THREADS*4);
#pragma unroll
        for (int it = 0; it < A_IT; it++) {
            int idx = (tid + it*THREADS) * 4;
            int r = idx / BK, c = idx % BK;
            float4 v = *(const float4*)&A[(size_t)(m0 + r)*K + k0 + c];
            As[c+0][r] = v.x; As[c+1][r] = v.y; As[c+2][r] = v.z; As[c+3][r] = v.w;
        }
        constexpr int B_IT = (BN*BK)/(THREADS*4);
#pragma unroll
        for (int it = 0; it < B_IT; it++) {
            int idx = (tid + it*THREADS) * 4;
            int r = idx / BK, c = idx % BK;
            float4 v = *(const float4*)&B[(size_t)(n0 + r)*K + k0 + c];
            Bs[c+0][r] = v.x; Bs[c+1][r] = v.y; Bs[c+2][r] = v.z; Bs[c+3][r] = v.w;
        }
        __syncthreads();

#pragma unroll
        for (int kk = 0; kk < BK; kk++) {
            float ra[TM], rb[TN];
            if constexpr (TM == 4) {
                *(float4*)&ra[0] = *(const float4*)&As[kk][ty*TM];
            } else {
                *(float2*)&ra[0] = *(const float2*)&As[kk][ty*TM];
            }
            *(float4*)&rb[0] = *(const float4*)&Bs[kk][tx*TN];
#pragma unroll
            for (int i = 0; i < TM; i++)
#pragma unroll
                for (int j = 0; j < TN; j++)
                    acc[i][j] = fmaf(ra[i], rb[j], acc[i][j]);
        }
        __syncthreads();
    }

#pragma unroll
    for (int i = 0; i < TM; i++) {
        int m = m0 + ty*TM + i;
        float* crow = C + (size_t)m * N + n0 + tx*TN;
#pragma unroll
        for (int j4 = 0; j4 < TN; j4 += 4) {
            float4 v;
            v.x = acc[i][j4+0] + bias[n0 + tx*TN + j4 + 0];
            v.y = acc[i][j4+1] + bias[n0 + tx*TN + j4 + 1];
            v.z = acc[i][j4+2] + bias[n0 + tx*TN + j4 + 2];
            v.w = acc[i][j4+3] + bias[n0 + tx*TN + j4 + 3];
            if constexpr (ACT == 1) {
                v.x = tanhf(v.x); v.y = tanhf(v.y); v.z = tanhf(v.z); v.w = tanhf(v.w);
            }
            *(float4*)&crow[j4] = v;
        }
    }
}

// ---------------- bf16 tensor-core GEMM for the output projection -----------
// C[M,N] = A[M,K] @ B[N,K]^T + bias.  A,B bf16 row-major. M%128==0, N%128==0, K%32==0.
// CTA tile 128x128x32, 8 warps (2 in M x 4 in N), warp tile 64x32.
// mma.sync.m16n8k16 bf16, fp32 accumulate. 2-stage cp.async pipeline.
// smem row stride 40 bf16 (80B): LDS.32 bank = (20*row + c) mod 32 -> conflict-free.
#define BSTR 40

__device__ __forceinline__ void mma_bf16(float* d, const unsigned* a, const unsigned* b) {
    asm volatile(
        "mma.sync.aligned.m16n8k16.row.col.f32.bf16.bf16.f32 "
        "{%0,%1,%2,%3}, {%4,%5,%6,%7}, {%8,%9}, {%0,%1,%2,%3};\n"
        : "+f"(d[0]), "+f"(d[1]), "+f"(d[2]), "+f"(d[3])
        : "r"(a[0]), "r"(a[1]), "r"(a[2]), "r"(a[3]),
          "r"(b[0]), "r"(b[1]));
}

__global__ __launch_bounds__(256)
void gemm_bf16_bias(const __nv_bfloat16* __restrict__ A, const __nv_bfloat16* __restrict__ B,
                    const float* __restrict__ bias, float* __restrict__ C,
                    int M, int N, int K)
{
    __shared__ __nv_bfloat16 As[2][128*BSTR];
    __shared__ __nv_bfloat16 Bs[2][128*BSTR];

    const int tid  = threadIdx.x;
    const int warp = tid >> 5;
    const int lane = tid & 31;
    const int g    = lane >> 2;
    const int c    = lane & 3;
    const int wm   = warp & 1;
    const int wn   = warp >> 1;
    const int m0   = blockIdx.y * 128;
    const int n0   = blockIdx.x * 128;

    float acc[4][4][4];
#pragma unroll
    for (int mi = 0; mi < 4; mi++)
#pragma unroll
        for (int ni = 0; ni < 4; ni++)
#pragma unroll
            for (int r = 0; r < 4; r++) acc[mi][ni][r] = 0.f;

    const int KT = K / 32;

    // stage loader: 128 rows x 32 bf16 (64B) per matrix = 512 x 16B chunks each
#define LOAD_STAGE(s, k0)                                                          \
    {                                                                              \
        _Pragma("unroll")                                                          \
        for (int it = 0; it < 2; it++) {                                           \
            int ch = tid + it*256;                                                 \
            int r  = ch >> 2;                                                      \
            int c8 = (ch & 3) * 8;                                                 \
            unsigned da = (unsigned)__cvta_generic_to_shared(&As[s][r*BSTR + c8]); \
            asm volatile("cp.async.cg.shared.global [%0], [%1], 16;\n"             \
                         :: "r"(da), "l"(&A[(size_t)(m0 + r)*K + (k0) + c8]));     \
            unsigned db = (unsigned)__cvta_generic_to_shared(&Bs[s][r*BSTR + c8]); \
            asm volatile("cp.async.cg.shared.global [%0], [%1], 16;\n"             \
                         :: "r"(db), "l"(&B[(size_t)(n0 + r)*K + (k0) + c8]));     \
        }                                                                          \
        asm volatile("cp.async.commit_group;\n");                                  \
    }

    LOAD_STAGE(0, 0);

    for (int kt = 0; kt < KT; kt++) {
        if (kt + 1 < KT) {
            LOAD_STAGE((kt + 1) & 1, (kt + 1) * 32);
            asm volatile("cp.async.wait_group 1;\n");
        } else {
            asm volatile("cp.async.wait_group 0;\n");
        }
        __syncthreads();

        const __nv_bfloat16* as = As[kt & 1];
        const __nv_bfloat16* bs = Bs[kt & 1];
#pragma unroll
        for (int ks = 0; ks < 32; ks += 16) {
            unsigned af[4][4], bf[4][2];
#pragma unroll
            for (int mi = 0; mi < 4; mi++) {
                int rb = wm*64 + mi*16;
                const unsigned* p0 = (const unsigned*)&as[(rb + g    )*BSTR + ks];
                const unsigned* p1 = (const unsigned*)&as[(rb + g + 8)*BSTR + ks];
                af[mi][0] = p0[c];
                af[mi][1] = p1[c];
                af[mi][2] = p0[c + 4];
                af[mi][3] = p1[c + 4];
            }
#pragma unroll
            for (int ni = 0; ni < 4; ni++) {
                int nb = wn*32 + ni*8;
                const unsigned* q = (const unsigned*)&bs[(nb + g)*BSTR + ks];
                bf[ni][0] = q[c];
                bf[ni][1] = q[c + 4];
            }
#pragma unroll
            for (int mi = 0; mi < 4; mi++)
#pragma unroll
                for (int ni = 0; ni < 4; ni++)
                    mma_bf16(acc[mi][ni], af[mi], bf[ni]);
        }
        __syncthreads();
    }

    // epilogue: bias + store
#pragma unroll
    for (int mi = 0; mi < 4; mi++) {
        int row = m0 + wm*64 + mi*16 + g;
#pragma unroll
        for (int ni = 0; ni < 4; ni++) {
            int col = n0 + wn*32 + ni*8 + c*2;
            float b0 = bias[col], b1 = bias[col+1];
            float2 v0 = make_float2(acc[mi][ni][0] + b0, acc[mi][ni][1] + b1);
            float2 v1 = make_float2(acc[mi][ni][2] + b0, acc[mi][ni][3] + b1);
            *(float2*)&C[(size_t)row      * N + col] = v0;
            *(float2*)&C[(size_t)(row + 8)* N + col] = v1;
        }
    }
#undef LOAD_STAGE
}

// fp32 -> bf16 conversion (n % 4 == 0)
__global__ void f32_to_bf16(const float* __restrict__ src, __nv_bfloat16* __restrict__ dst, int n)
{
    int i = (blockIdx.x * blockDim.x + threadIdx.x) * 4;
    if (i < n) {
        float4 v = *(const float4*)&src[i];
        __nv_bfloat162 lo = __floats2bfloat162_rn(v.x, v.y);
        __nv_bfloat162 hi = __floats2bfloat162_rn(v.z, v.w);
        *(__nv_bfloat162*)&dst[i]     = lo;
        *(__nv_bfloat162*)&dst[i + 2] = hi;
    }
}

// ---------------- small kernels ----------------
__global__ void zero_kernel(float* __restrict__ p, int n) {
    int i = blockIdx.x * blockDim.x + threadIdx.x;
    if (i < n) p[i] = 0.f;
}

__global__ void gather_emb(const int* __restrict__ y, const float* __restrict__ emb,
                           float* __restrict__ Yemb)
{
    int row = blockIdx.x;
    int r = y[row];
    const float4* src = (const float4*)(emb + (size_t)r * DIN);
    float4* dst = (float4*)(Yemb + (size_t)row * DIN);
    for (int j = threadIdx.x; j < DIN/4; j += blockDim.x) dst[j] = src[j];
}

__device__ __forceinline__ float sigmoidf_(float x) { return 1.f / (1.f + __expf(-x)); }

__global__ void gru_gate(const float* __restrict__ GIt, const float* __restrict__ GH,
                         const float* __restrict__ Hprev, float* __restrict__ Hnext)
{
    int idx = blockIdx.x * blockDim.x + threadIdx.x;
    int b = idx >> 9;
    int j = idx & 511;
    const float* gi = GIt + (size_t)b * G3H;
    const float* gh = GH  + (size_t)b * G3H;
    float r = sigmoidf_(gi[j]        + gh[j]);
    float z = sigmoidf_(gi[HID + j]  + gh[HID + j]);
    float n = tanhf    (gi[2*HID + j] + r * gh[2*HID + j]);
    float h = Hprev[idx];
    Hnext[idx] = (1.f - z) * n + z * h;
}

__global__ void mul_ct(const float* __restrict__ H, const float* __restrict__ ct,
                       float* __restrict__ X)
{
    int i = blockIdx.x * blockDim.x + threadIdx.x;
    X[i] = H[i + BH] * ct[i & (BH - 1)];
}

__global__ void attn_kernel(const float* __restrict__ Q, const float* __restrict__ K,
                            const float* __restrict__ V, float* __restrict__ O)
{
    int row = blockIdx.x;
    int tid = threadIdx.x;
    __shared__ float q[512], k[512], v[512], sc[64], w[64];
    const float* qr = Q + (size_t)row * HID;
    const float* kr = K + (size_t)row * HID;
    const float* vr = V + (size_t)row * HID;
    for (int i = tid; i < HID; i += 64) { q[i] = qr[i]; k[i] = kr[i]; v[i] = vr[i]; }
    __syncthreads();
    {
        int h = tid >> 3, gg = tid & 7;
        float s = 0.f;
#pragma unroll
        for (int d = 0; d < 64; d++) s = fmaf(q[h*64+d], k[gg*64+d], s);
        sc[tid] = s * (1.f / 64.f);
    }
    __syncthreads();
    if (tid < 8) {
        float m = -1e30f;
#pragma unroll
        for (int gg = 0; gg < 8; gg++) m = fmaxf(m, sc[tid*8+gg]);
        float e[8], s = 0.f;
#pragma unroll
        for (int gg = 0; gg < 8; gg++) { e[gg] = __expf(sc[tid*8+gg] - m); s += e[gg]; }
        float inv = 1.f / s;
#pragma unroll
        for (int gg = 0; gg < 8; gg++) w[tid*8+gg] = e[gg] * inv;
    }
    __syncthreads();
    {
        int h = tid >> 3, d0 = (tid & 7) * 8;
        float o[8];
#pragma unroll
        for (int d = 0; d < 8; d++) o[d] = 0.f;
#pragma unroll
        for (int gg = 0; gg < 8; gg++) {
            float wg = w[h*8+gg];
#pragma unroll
            for (int d = 0; d < 8; d++) o[d] = fmaf(wg, v[gg*64 + d0 + d], o[d]);
        }
        float* orow = O + (size_t)row * HID + h*64 + d0;
#pragma unroll
        for (int d = 0; d < 8; d++) orow[d] = o[d];
    }
}

__global__ void softmax_rows(float* __restrict__ C)
{
    float* row = C + (size_t)blockIdx.x * VOCAB;
    int tid = threadIdx.x;
    __shared__ float red[256];
    float m = -1e30f;
    for (int j = tid; j < VOCAB; j += 256) m = fmaxf(m, row[j]);
    red[tid] = m; __syncthreads();
    for (int s = 128; s > 0; s >>= 1) { if (tid < s) red[tid] = fmaxf(red[tid], red[tid+s]); __syncthreads(); }
    m = red[0]; __syncthreads();
    float s = 0.f;
    for (int j = tid; j < VOCAB; j += 256) s += __expf(row[j] - m);
    red[tid] = s; __syncthreads();
    for (int st = 128; st > 0; st >>= 1) { if (tid < st) red[tid] += red[tid+st]; __syncthreads(); }
    float inv = 1.f / red[0];
    __syncthreads();
    for (int j = tid; j < VOCAB; j += 256) row[j] = __expf(row[j] - m) * inv;
}

// ---------------- launch ----------------
extern "C" void kernel_launch(void* const* d_in, const int* in_sizes, int n_in,
                              void* d_out, int out_size)
{
    const int*   y     = (const int*)  d_in[0];
    const float* ctx   = (const float*)d_in[1];
    const float* emb   = (const float*)d_in[2];
    const float* W_ih  = (const float*)d_in[3];
    const float* b_ih  = (const float*)d_in[4];
    const float* W_hh  = (const float*)d_in[5];
    const float* b_hh  = (const float*)d_in[6];
    const float* W_att = (const float*)d_in[7];
    const float* b_att = (const float*)d_in[8];
    const float* Wq    = (const float*)d_in[9];
    const float* bq    = (const float*)d_in[10];
    const float* Wk    = (const float*)d_in[11];
    const float* bk    = (const float*)d_in[12];
    const float* Wv    = (const float*)d_in[13];
    const float* bv    = (const float*)d_in[14];
    const float* Wfc   = (const float*)d_in[15];
    const float* bfc   = (const float*)d_in[16];
    const float* W_h2o = (const float*)d_in[17];
    const float* b_h2o = (const float*)d_in[18];
    const float* W_out = (const float*)d_in[19];
    const float* b_out = (const float*)d_in[20];
    float* out = (float*)d_out;

    float *pYemb, *pGI, *pct, *pGH, *pH, *pX, *pQ, *pK, *pV, *pATT, *pH2, *pLOGIT;
    __nv_bfloat16 *pLOGIT_BF, *pWOUT_BF;
    cudaGetSymbolAddress((void**)&pYemb,  g_Yemb);
    cudaGetSymbolAddress((void**)&pGI,    g_GI);
    cudaGetSymbolAddress((void**)&pct,    g_ct);
    cudaGetSymbolAddress((void**)&pGH,    g_GH);
    cudaGetSymbolAddress((void**)&pH,     g_H);
    cudaGetSymbolAddress((void**)&pX,     g_X);
    cudaGetSymbolAddress((void**)&pQ,     g_Q);
    cudaGetSymbolAddress((void**)&pK,     g_Kb);
    cudaGetSymbolAddress((void**)&pV,     g_V);
    cudaGetSymbolAddress((void**)&pATT,   g_ATT);
    cudaGetSymbolAddress((void**)&pH2,    g_H2);
    cudaGetSymbolAddress((void**)&pLOGIT, g_LOGIT);
    cudaGetSymbolAddress((void**)&pLOGIT_BF, g_LOGIT_BF);
    cudaGetSymbolAddress((void**)&pWOUT_BF,  g_WOUT_BF);

    zero_kernel<<<BH/256, 256>>>(pH, BH);
    gather_emb<<<ROWS, 128>>>(y, emb, pYemb);

    // convert W_out to bf16 (early; independent of everything else)
    f32_to_bf16<<<(VOCAB*DIN/4 + 255)/256, 256>>>(W_out, pWOUT_BF, VOCAB*DIN);

    // ct = tanh(ctx @ W_att^T + b_att)
    {
        dim3 grid(HID/64, BATCH/64);
        sgemm_tn<64,64,16,4,4,1><<<grid, 256>>>(ctx, W_att, b_att, pct, BATCH, HID, FFEAT);
    }

    // GI = Yemb @ W_ih^T + b_ih
    {
        dim3 grid(G3H/64, ROWS/64);
        sgemm_tn<64,64,16,4,4,0><<<grid, 256>>>(pYemb, W_ih, b_ih, pGI, ROWS, G3H, DIN);
    }

    // sequential GRU scan
    for (int t = 0; t < T_STEPS; t++) {
        dim3 grid(G3H/64, BATCH/16);
        sgemm_tn<16,64,32,2,4,0><<<grid, 128>>>(pH + (size_t)t*BH, W_hh, b_hh, pGH,
                                                BATCH, G3H, HID);
        gru_gate<<<BH/256, 256>>>(pGI + (size_t)t*BATCH*G3H, pGH,
                                  pH + (size_t)t*BH, pH + (size_t)(t+1)*BH);
    }

    mul_ct<<<(ROWS*HID)/256, 256>>>(pH, pct, pX);

    // Q/K/V projections
    {
        dim3 grid(HID/64, ROWS/64);
        sgemm_tn<64,64,16,4,4,0><<<grid, 256>>>(pX, Wq, bq, pQ, ROWS, HID, HID);
        sgemm_tn<64,64,16,4,4,0><<<grid, 256>>>(pX, Wk, bk, pK, ROWS, HID, HID);
        sgemm_tn<64,64,16,4,4,0><<<grid, 256>>>(pX, Wv, bv, pV, ROWS, HID, HID);
    }

    attn_kernel<<<ROWS, 64>>>(pQ, pK, pV, pATT);

    // h2 = att @ Wfc^T + bfc
    {
        dim3 grid(HID/64, ROWS/64);
        sgemm_tn<64,64,16,4,4,0><<<grid, 256>>>(pATT, Wfc, bfc, pH2, ROWS, HID, HID);
    }

    // logit = tanh(h2 @ W_h2o^T + b_h2o)
    {
        dim3 grid(DIN/64, ROWS/64);
        sgemm_tn<64,64,16,4,4,1><<<grid, 256>>>(pH2, W_h2o, b_h2o, pLOGIT, ROWS, DIN, HID);
    }

    // convert logit to bf16
    f32_to_bf16<<<(ROWS*DIN/4 + 255)/256, 256>>>(pLOGIT, pLOGIT_BF, ROWS*DIN);

    // scores = logit @ W_out^T + b_out  (bf16 tensor cores, 2-stage cp.async)
    {
        dim3 grid(VOCAB/128, ROWS/128);   // (250, 16)
        gemm_bf16_bias<<<grid, 256>>>(pLOGIT_BF, pWOUT_BF, b_out, out, ROWS, VOCAB, DIN);
    }

    softmax_rows<<<ROWS, 256>>>(out);
}

// round 9
// speedup vs baseline: 2.1757x; 1.2156x over previous
#include <cuda_runtime.h>
#include <cuda_bf16.h>
#include <math.h>

// Problem constants
#define T_STEPS 32
#define BATCH   64
#define DIN     512
#define HID     512
#define VOCAB   32000
#define FFEAT   768
#define G3H     1536            // 3*HID
#define ROWS    (T_STEPS*BATCH) // 2048
#define BH      (BATCH*HID)     // 32768

// ---------------- scratch (static device globals; no allocs) ----------------
__device__ __nv_bfloat16 g_YembBF [ROWS*DIN];
__device__ float         g_GI     [ROWS*G3H];
__device__ float         g_ctp    [128*HID];        // padded ct (rows 0..63 valid)
__device__ float         g_GH     [BATCH*G3H];
__device__ float         g_H      [(T_STEPS+1)*BH]; // slot 0 = h0 = 0
__device__ __nv_bfloat16 g_XBF    [ROWS*HID];
__device__ float         g_QKV    [ROWS*G3H];       // q|k|v concat per row
__device__ __nv_bfloat16 g_ATTBF  [ROWS*HID];
__device__ __nv_bfloat16 g_H2BF   [ROWS*HID];
__device__ __nv_bfloat16 g_LOGITBF[ROWS*DIN];
// bf16 weights
__device__ __nv_bfloat16 g_WihBF  [G3H*DIN];
__device__ __nv_bfloat16 g_WattBF [HID*FFEAT];
__device__ __nv_bfloat16 g_WqkvBF [G3H*HID];        // Wq|Wk|Wv stacked rows
__device__ float         g_bqkv   [G3H];
__device__ __nv_bfloat16 g_WfcBF  [HID*HID];
__device__ __nv_bfloat16 g_Wh2oBF [DIN*HID];
__device__ __nv_bfloat16 g_WoutBF [VOCAB*DIN];
__device__ __nv_bfloat16 g_CTXP   [128*FFEAT];      // ctx padded to 128 rows

// ---------------- fp32 SGEMM (kept for the GRU scan only) -------------------
template<int BM,int BN,int BK,int TM,int TN>
__global__ void sgemm_tn(const float* __restrict__ A, const float* __restrict__ B,
                         const float* __restrict__ bias, float* __restrict__ C,
                         int M, int N, int K)
{
    constexpr int THREADS = (BM/TM)*(BN/TN);
    constexpr int NTX = BN/TN;
    __shared__ float As[BK][BM+4];
    __shared__ float Bs[BK][BN+4];

    const int tid = threadIdx.x;
    const int m0 = blockIdx.y * BM;
    const int n0 = blockIdx.x * BN;
    const int tx = tid % NTX;
    const int ty = tid / NTX;

    float acc[TM][TN];
#pragma unroll
    for (int i = 0; i < TM; i++)
#pragma unroll
        for (int j = 0; j < TN; j++) acc[i][j] = 0.f;

    for (int k0 = 0; k0 < K; k0 += BK) {
        constexpr int A_IT = (BM*BK)/(THREADS*4);
#pragma unroll
        for (int it = 0; it < A_IT; it++) {
            int idx = (tid + it*THREADS) * 4;
            int r = idx / BK, c = idx % BK;
            float4 v = *(const float4*)&A[(size_t)(m0 + r)*K + k0 + c];
            As[c+0][r] = v.x; As[c+1][r] = v.y; As[c+2][r] = v.z; As[c+3][r] = v.w;
        }
        constexpr int B_IT = (BN*BK)/(THREADS*4);
#pragma unroll
        for (int it = 0; it < B_IT; it++) {
            int idx = (tid + it*THREADS) * 4;
            int r = idx / BK, c = idx % BK;
            float4 v = *(const float4*)&B[(size_t)(n0 + r)*K + k0 + c];
            Bs[c+0][r] = v.x; Bs[c+1][r] = v.y; Bs[c+2][r] = v.z; Bs[c+3][r] = v.w;
        }
        __syncthreads();

#pragma unroll
        for (int kk = 0; kk < BK; kk++) {
            float ra[TM], rb[TN];
#pragma unroll
            for (int i = 0; i < TM; i++) ra[i] = As[kk][ty*TM + i];
#pragma unroll
            for (int j = 0; j < TN; j++) rb[j] = Bs[kk][tx*TN + j];
#pragma unroll
            for (int i = 0; i < TM; i++)
#pragma unroll
                for (int j = 0; j < TN; j++)
                    acc[i][j] = fmaf(ra[i], rb[j], acc[i][j]);
        }
        __syncthreads();
    }

#pragma unroll
    for (int i = 0; i < TM; i++) {
        int m = m0 + ty*TM + i;
        float* crow = C + (size_t)m * N + n0 + tx*TN;
#pragma unroll
        for (int j = 0; j < TN; j++) crow[j] = acc[i][j] + bias[n0 + tx*TN + j];
    }
}

// ---------------- bf16 tensor-core GEMM (ldmatrix + 3-stage cp.async) -------
// C[M,N] = A[M,K] @ B[N,K]^T + bias (+tanh).  A,B bf16 row-major.
// M%128==0, N%BN==0, K%32==0. BM=128, BK=32, 8 warps (2M x 4N), warp tile 64x(BN/4).
// smem row stride 40 bf16 (80B) -> ldmatrix phases hit all 32 banks.
#define BSTR 40

__device__ __forceinline__ void mma_bf16(float* d, const unsigned* a, const unsigned* b) {
    asm volatile(
        "mma.sync.aligned.m16n8k16.row.col.f32.bf16.bf16.f32 "
        "{%0,%1,%2,%3}, {%4,%5,%6,%7}, {%8,%9}, {%0,%1,%2,%3};\n"
        : "+f"(d[0]), "+f"(d[1]), "+f"(d[2]), "+f"(d[3])
        : "r"(a[0]), "r"(a[1]), "r"(a[2]), "r"(a[3]),
          "r"(b[0]), "r"(b[1]));
}

__device__ __forceinline__ void ldsm_x4(unsigned& r0, unsigned& r1, unsigned& r2, unsigned& r3,
                                        unsigned addr) {
    asm volatile("ldmatrix.sync.aligned.m8n8.x4.shared.b16 {%0,%1,%2,%3}, [%4];"
                 : "=r"(r0), "=r"(r1), "=r"(r2), "=r"(r3) : "r"(addr));
}

template<int BN, int ACT, int OUTBF>
__global__ __launch_bounds__(256, 1)
void gemm_bf16_tc(const __nv_bfloat16* __restrict__ A, const __nv_bfloat16* __restrict__ B,
                  const float* __restrict__ bias, void* __restrict__ Cout,
                  int M, int N, int K)
{
    extern __shared__ __nv_bfloat16 smem[];
    constexpr int WN    = BN / 4;          // warp n-extent
    constexpr int NI    = WN / 8;          // 8-wide n blocks per warp
    constexpr int STAGE = (128 + BN) * BSTR;

    const int tid  = threadIdx.x;
    const int warp = tid >> 5;
    const int lane = tid & 31;
    const int g    = lane >> 2;
    const int c    = lane & 3;
    const int wm   = warp & 1;
    const int wn   = warp >> 1;
    const int m0   = blockIdx.y * 128;
    const int n0   = blockIdx.x * BN;

    float acc[4][NI][4];
#pragma unroll
    for (int mi = 0; mi < 4; mi++)
#pragma unroll
        for (int ni = 0; ni < NI; ni++)
#pragma unroll
            for (int r = 0; r < 4; r++) acc[mi][ni][r] = 0.f;

    const int KT = K / 32;

    // per-stage async loader: A 128x32 bf16 + B BNx32 bf16, 16B chunks
    auto load_stage = [&](int s, int k0) {
        __nv_bfloat16* sa = smem + s * STAGE;
        __nv_bfloat16* sb = sa + 128 * BSTR;
        constexpr int TOT = (128 + BN) * 4;
#pragma unroll
        for (int it = 0; it < TOT / 256; it++) {
            int idx = tid + it * 256;
            const __nv_bfloat16* src;
            __nv_bfloat16* dst;
            if (idx < 512) {
                int r = idx >> 2, c8 = (idx & 3) * 8;
                src = &A[(size_t)(m0 + r) * K + k0 + c8];
                dst = &sa[r * BSTR + c8];
            } else {
                int j = idx - 512;
                int r = j >> 2, c8 = (j & 3) * 8;
                src = &B[(size_t)(n0 + r) * K + k0 + c8];
                dst = &sb[r * BSTR + c8];
            }
            unsigned d = (unsigned)__cvta_generic_to_shared(dst);
            asm volatile("cp.async.cg.shared.global [%0], [%1], 16;\n" :: "r"(d), "l"(src));
        }
        asm volatile("cp.async.commit_group;\n");
    };

    load_stage(0, 0);
    load_stage(1, 32);

    for (int kt = 0; kt < KT; kt++) {
        if (kt == KT - 1) asm volatile("cp.async.wait_group 0;\n");
        else              asm volatile("cp.async.wait_group 1;\n");
        __syncthreads();
        if (kt + 2 < KT) load_stage((kt + 2) % 3, (kt + 2) * 32);

        const __nv_bfloat16* sa = smem + (kt % 3) * STAGE;
        const __nv_bfloat16* sb = sa + 128 * BSTR;
#pragma unroll
        for (int ks = 0; ks < 32; ks += 16) {
            unsigned af[4][4];
#pragma unroll
            for (int mi = 0; mi < 4; mi++) {
                int row = wm * 64 + mi * 16 + (lane & 15);
                int col = ks + ((lane >> 4) << 3);
                unsigned addr = (unsigned)__cvta_generic_to_shared(&sa[row * BSTR + col]);
                ldsm_x4(af[mi][0], af[mi][1], af[mi][2], af[mi][3], addr);
            }
            unsigned bf[NI][2];
#pragma unroll
            for (int p = 0; p < NI / 2; p++) {
                int row = wn * WN + p * 16 + ((lane >> 4) << 3) + (lane & 7);
                int col = ks + (((lane >> 3) & 1) << 3);
                unsigned addr = (unsigned)__cvta_generic_to_shared(&sb[row * BSTR + col]);
                unsigned r0, r1, r2, r3;
                ldsm_x4(r0, r1, r2, r3, addr);
                bf[2*p][0] = r0; bf[2*p][1] = r1;
                bf[2*p+1][0] = r2; bf[2*p+1][1] = r3;
            }
#pragma unroll
            for (int mi = 0; mi < 4; mi++)
#pragma unroll
                for (int ni = 0; ni < NI; ni++)
                    mma_bf16(acc[mi][ni], af[mi], bf[ni]);
        }
        __syncthreads();
    }

    // epilogue
#pragma unroll
    for (int mi = 0; mi < 4; mi++) {
        int row = m0 + wm * 64 + mi * 16 + g;
#pragma unroll
        for (int ni = 0; ni < NI; ni++) {
            int col = n0 + wn * WN + ni * 8 + c * 2;
            float b0 = bias[col], b1 = bias[col + 1];
            float v00 = acc[mi][ni][0] + b0, v01 = acc[mi][ni][1] + b1;
            float v10 = acc[mi][ni][2] + b0, v11 = acc[mi][ni][3] + b1;
            if (ACT == 1) { v00 = tanhf(v00); v01 = tanhf(v01); v10 = tanhf(v10); v11 = tanhf(v11); }
            if (OUTBF) {
                __nv_bfloat16* Cb = (__nv_bfloat16*)Cout;
                *(__nv_bfloat162*)&Cb[(size_t)row       * N + col] = __floats2bfloat162_rn(v00, v01);
                *(__nv_bfloat162*)&Cb[(size_t)(row + 8) * N + col] = __floats2bfloat162_rn(v10, v11);
            } else {
                float* Cf = (float*)Cout;
                *(float2*)&Cf[(size_t)row       * N + col] = make_float2(v00, v01);
                *(float2*)&Cf[(size_t)(row + 8) * N + col] = make_float2(v10, v11);
            }
        }
    }
}

// ---------------- small kernels ----------------
__global__ void zero_kernel(float* __restrict__ p, int n) {
    int i = blockIdx.x * blockDim.x + threadIdx.x;
    if (i < n) p[i] = 0.f;
}

__global__ void f32_to_bf16(const float* __restrict__ src, __nv_bfloat16* __restrict__ dst, int n)
{
    int i = (blockIdx.x * blockDim.x + threadIdx.x) * 4;
    if (i < n) {
        float4 v = *(const float4*)&src[i];
        *(__nv_bfloat162*)&dst[i]     = __floats2bfloat162_rn(v.x, v.y);
        *(__nv_bfloat162*)&dst[i + 2] = __floats2bfloat162_rn(v.z, v.w);
    }
}

// pad ctx [64,FFEAT] fp32 -> [128,FFEAT] bf16 (rows 64..127 zero)
__global__ void pad_ctx_bf16(const float* __restrict__ ctx, __nv_bfloat16* __restrict__ dst)
{
    int i = (blockIdx.x * blockDim.x + threadIdx.x) * 2;   // over 128*FFEAT
    if (i < 128 * FFEAT) {
        int r = i / FFEAT;
        __nv_bfloat162 v;
        if (r < 64) {
            float2 f = *(const float2*)&ctx[(size_t)r * FFEAT + (i % FFEAT)];
            v = __floats2bfloat162_rn(f.x, f.y);
        } else {
            v = __floats2bfloat162_rn(0.f, 0.f);
        }
        *(__nv_bfloat162*)&dst[i] = v;
    }
}

__global__ void concat_bias3(const float* __restrict__ a, const float* __restrict__ b,
                             const float* __restrict__ c, float* __restrict__ dst)
{
    int i = blockIdx.x * blockDim.x + threadIdx.x;
    if (i < HID) { dst[i] = a[i]; dst[HID + i] = b[i]; dst[2*HID + i] = c[i]; }
}

// gather embedding rows -> bf16
__global__ void gather_emb_bf16(const int* __restrict__ y, const float* __restrict__ emb,
                                __nv_bfloat16* __restrict__ Yemb)
{
    int row = blockIdx.x;
    int r = y[row];
    const float4* src = (const float4*)(emb + (size_t)r * DIN);
    __nv_bfloat16* dst = Yemb + (size_t)row * DIN;
    for (int j = threadIdx.x; j < DIN/4; j += blockDim.x) {
        float4 v = src[j];
        *(__nv_bfloat162*)&dst[j*4]     = __floats2bfloat162_rn(v.x, v.y);
        *(__nv_bfloat162*)&dst[j*4 + 2] = __floats2bfloat162_rn(v.z, v.w);
    }
}

__device__ __forceinline__ float sigmoidf_(float x) { return 1.f / (1.f + __expf(-x)); }

__global__ void gru_gate(const float* __restrict__ GIt, const float* __restrict__ GH,
                         const float* __restrict__ Hprev, float* __restrict__ Hnext)
{
    int idx = blockIdx.x * blockDim.x + threadIdx.x;
    int b = idx >> 9;
    int j = idx & 511;
    const float* gi = GIt + (size_t)b * G3H;
    const float* gh = GH  + (size_t)b * G3H;
    float r = sigmoidf_(gi[j]        + gh[j]);
    float z = sigmoidf_(gi[HID + j]  + gh[HID + j]);
    float n = tanhf    (gi[2*HID + j] + r * gh[2*HID + j]);
    float h = Hprev[idx];
    Hnext[idx] = (1.f - z) * n + z * h;
}

// X[t*B+b,:] = h1[t][b,:] * ct[b,:]  -> bf16
__global__ void mul_ct_bf16(const float* __restrict__ H, const float* __restrict__ ct,
                            __nv_bfloat16* __restrict__ X)
{
    int i = (blockIdx.x * blockDim.x + threadIdx.x) * 2;
    float2 h = *(const float2*)&H[i + BH];
    float2 cc = *(const float2*)&ct[i & (BH - 1)];
    *(__nv_bfloat162*)&X[i] = __floats2bfloat162_rn(h.x * cc.x, h.y * cc.y);
}

// per-(t,b) 8-head attention; QKV concat rows [q|k|v], writes bf16
__global__ void attn_kernel(const float* __restrict__ QKV, __nv_bfloat16* __restrict__ O)
{
    int row = blockIdx.x;
    int tid = threadIdx.x;  // 64
    __shared__ float q[512], k[512], v[512], sc[64], w[64];
    const float* base = QKV + (size_t)row * G3H;
    for (int i = tid; i < HID; i += 64) {
        q[i] = base[i]; k[i] = base[HID + i]; v[i] = base[2*HID + i];
    }
    __syncthreads();
    {
        int h = tid >> 3, gg = tid & 7;
        float s = 0.f;
#pragma unroll
        for (int d = 0; d < 64; d++) s = fmaf(q[h*64+d], k[gg*64+d], s);
        sc[tid] = s * (1.f / 64.f);
    }
    __syncthreads();
    if (tid < 8) {
        float m = -1e30f;
#pragma unroll
        for (int gg = 0; gg < 8; gg++) m = fmaxf(m, sc[tid*8+gg]);
        float e[8], s = 0.f;
#pragma unroll
        for (int gg = 0; gg < 8; gg++) { e[gg] = __expf(sc[tid*8+gg] - m); s += e[gg]; }
        float inv = 1.f / s;
#pragma unroll
        for (int gg = 0; gg < 8; gg++) w[tid*8+gg] = e[gg] * inv;
    }
    __syncthreads();
    {
        int h = tid >> 3, d0 = (tid & 7) * 8;
        float o[8];
#pragma unroll
        for (int d = 0; d < 8; d++) o[d] = 0.f;
#pragma unroll
        for (int gg = 0; gg < 8; gg++) {
            float wg = w[h*8+gg];
#pragma unroll
            for (int d = 0; d < 8; d++) o[d] = fmaf(wg, v[gg*64 + d0 + d], o[d]);
        }
        __nv_bfloat16* orow = O + (size_t)row * HID + h*64 + d0;
#pragma unroll
        for (int d = 0; d < 8; d += 2)
            *(__nv_bfloat162*)&orow[d] = __floats2bfloat162_rn(o[d], o[d+1]);
    }
}

__global__ void softmax_rows(float* __restrict__ C)
{
    float* row = C + (size_t)blockIdx.x * VOCAB;
    int tid = threadIdx.x;
    __shared__ float red[256];
    float m = -1e30f;
    for (int j = tid; j < VOCAB; j += 256) m = fmaxf(m, row[j]);
    red[tid] = m; __syncthreads();
    for (int s = 128; s > 0; s >>= 1) { if (tid < s) red[tid] = fmaxf(red[tid], red[tid+s]); __syncthreads(); }
    m = red[0]; __syncthreads();
    float s = 0.f;
    for (int j = tid; j < VOCAB; j += 256) s += __expf(row[j] - m);
    red[tid] = s; __syncthreads();
    for (int st = 128; st > 0; st >>= 1) { if (tid < st) red[tid] += red[tid+st]; __syncthreads(); }
    float inv = 1.f / red[0];
    __syncthreads();
    for (int j = tid; j < VOCAB; j += 256) row[j] = __expf(row[j] - m) * inv;
}

// ---------------- launch ----------------
extern "C" void kernel_launch(void* const* d_in, const int* in_sizes, int n_in,
                              void* d_out, int out_size)
{
    const int*   y     = (const int*)  d_in[0];
    const float* ctx   = (const float*)d_in[1];
    const float* emb   = (const float*)d_in[2];
    const float* W_ih  = (const float*)d_in[3];
    const float* b_ih  = (const float*)d_in[4];
    const float* W_hh  = (const float*)d_in[5];
    const float* b_hh  = (const float*)d_in[6];
    const float* W_att = (const float*)d_in[7];
    const float* b_att = (const float*)d_in[8];
    const float* Wq    = (const float*)d_in[9];
    const float* bq    = (const float*)d_in[10];
    const float* Wk    = (const float*)d_in[11];
    const float* bk    = (const float*)d_in[12];
    const float* Wv    = (const float*)d_in[13];
    const float* bv    = (const float*)d_in[14];
    const float* Wfc   = (const float*)d_in[15];
    const float* bfc   = (const float*)d_in[16];
    const float* W_h2o = (const float*)d_in[17];
    const float* b_h2o = (const float*)d_in[18];
    const float* W_out = (const float*)d_in[19];
    const float* b_out = (const float*)d_in[20];
    float* out = (float*)d_out;

    __nv_bfloat16 *pYembBF, *pXBF, *pATTBF, *pH2BF, *pLOGITBF;
    __nv_bfloat16 *pWihBF, *pWattBF, *pWqkvBF, *pWfcBF, *pWh2oBF, *pWoutBF, *pCTXP;
    float *pGI, *pctp, *pGH, *pH, *pQKV, *pbqkv;
    cudaGetSymbolAddress((void**)&pYembBF,  g_YembBF);
    cudaGetSymbolAddress((void**)&pGI,      g_GI);
    cudaGetSymbolAddress((void**)&pctp,     g_ctp);
    cudaGetSymbolAddress((void**)&pGH,      g_GH);
    cudaGetSymbolAddress((void**)&pH,       g_H);
    cudaGetSymbolAddress((void**)&pXBF,     g_XBF);
    cudaGetSymbolAddress((void**)&pQKV,     g_QKV);
    cudaGetSymbolAddress((void**)&pATTBF,   g_ATTBF);
    cudaGetSymbolAddress((void**)&pH2BF,    g_H2BF);
    cudaGetSymbolAddress((void**)&pLOGITBF, g_LOGITBF);
    cudaGetSymbolAddress((void**)&pWihBF,   g_WihBF);
    cudaGetSymbolAddress((void**)&pWattBF,  g_WattBF);
    cudaGetSymbolAddress((void**)&pWqkvBF,  g_WqkvBF);
    cudaGetSymbolAddress((void**)&pbqkv,    g_bqkv);
    cudaGetSymbolAddress((void**)&pWfcBF,   g_WfcBF);
    cudaGetSymbolAddress((void**)&pWh2oBF,  g_Wh2oBF);
    cudaGetSymbolAddress((void**)&pWoutBF,  g_WoutBF);
    cudaGetSymbolAddress((void**)&pCTXP,    g_CTXP);

    // dynamic smem limits for the bf16 GEMM instantiations
    const int SM128 = 3 * (128 + 128) * BSTR * 2;   // 61440
    const int SM256 = 3 * (128 + 256) * BSTR * 2;   // 92160
    cudaFuncSetAttribute(gemm_bf16_tc<128,0,0>, cudaFuncAttributeMaxDynamicSharedMemorySize, SM128);
    cudaFuncSetAttribute(gemm_bf16_tc<128,1,0>, cudaFuncAttributeMaxDynamicSharedMemorySize, SM128);
    cudaFuncSetAttribute(gemm_bf16_tc<128,0,1>, cudaFuncAttributeMaxDynamicSharedMemorySize, SM128);
    cudaFuncSetAttribute(gemm_bf16_tc<128,1,1>, cudaFuncAttributeMaxDynamicSharedMemorySize, SM128);
    cudaFuncSetAttribute(gemm_bf16_tc<256,0,0>, cudaFuncAttributeMaxDynamicSharedMemorySize, SM256);

    // ---- conversions / setup ----
    zero_kernel<<<BH/256, 256>>>(pH, BH);
    f32_to_bf16<<<(G3H*DIN/4   + 255)/256, 256>>>(W_ih,  pWihBF,  G3H*DIN);
    f32_to_bf16<<<(HID*FFEAT/4 + 255)/256, 256>>>(W_att, pWattBF, HID*FFEAT);
    f32_to_bf16<<<(HID*HID/4   + 255)/256, 256>>>(Wq,    pWqkvBF,             HID*HID);
    f32_to_bf16<<<(HID*HID/4   + 255)/256, 256>>>(Wk,    pWqkvBF + HID*HID,   HID*HID);
    f32_to_bf16<<<(HID*HID/4   + 255)/256, 256>>>(Wv,    pWqkvBF + 2*HID*HID, HID*HID);
    concat_bias3<<<(HID + 255)/256, 256>>>(bq, bk, bv, pbqkv);
    f32_to_bf16<<<(HID*HID/4   + 255)/256, 256>>>(Wfc,   pWfcBF,  HID*HID);
    f32_to_bf16<<<(DIN*HID/4   + 255)/256, 256>>>(W_h2o, pWh2oBF, DIN*HID);
    f32_to_bf16<<<(VOCAB*DIN/4 + 255)/256, 256>>>(W_out, pWoutBF, VOCAB*DIN);
    pad_ctx_bf16<<<(128*FFEAT/2 + 255)/256, 256>>>(ctx, pCTXP);
    gather_emb_bf16<<<ROWS, 128>>>(y, emb, pYembBF);

    // ct = tanh(ctxp @ W_att^T + b_att)  [128(pad),512] K=768
    {
        dim3 grid(HID/128, 1);
        gemm_bf16_tc<128,1,0><<<grid, 256, SM128>>>(pCTXP, pWattBF, b_att, pctp, 128, HID, FFEAT);
    }
    // GI = Yemb @ W_ih^T + b_ih   [2048,1536] K=512
    {
        dim3 grid(G3H/128, ROWS/128);
        gemm_bf16_tc<128,0,0><<<grid, 256, SM128>>>(pYembBF, pWihBF, b_ih, pGI, ROWS, G3H, DIN);
    }

    // sequential GRU scan (fp32)
    for (int t = 0; t < T_STEPS; t++) {
        dim3 grid(G3H/64, BATCH/16);
        sgemm_tn<16,64,32,2,4><<<grid, 128>>>(pH + (size_t)t*BH, W_hh, b_hh, pGH,
                                              BATCH, G3H, HID);
        gru_gate<<<BH/256, 256>>>(pGI + (size_t)t*BATCH*G3H, pGH,
                                  pH + (size_t)t*BH, pH + (size_t)(t+1)*BH);
    }

    mul_ct_bf16<<<(ROWS*HID/2)/256, 256>>>(pH, pctp, pXBF);

    // QKV fused: [2048,1536] K=512
    {
        dim3 grid(G3H/128, ROWS/128);
        gemm_bf16_tc<128,0,0><<<grid, 256, SM128>>>(pXBF, pWqkvBF, pbqkv, pQKV, ROWS, G3H, HID);
    }

    attn_kernel<<<ROWS, 64>>>(pQKV, pATTBF);

    // h2 = att @ Wfc^T + bfc -> bf16
    {
        dim3 grid(HID/128, ROWS/128);
        gemm_bf16_tc<128,0,1><<<grid, 256, SM128>>>(pATTBF, pWfcBF, bfc, pH2BF, ROWS, HID, HID);
    }
    // logit = tanh(h2 @ W_h2o^T + b_h2o) -> bf16
    {
        dim3 grid(DIN/128, ROWS/128);
        gemm_bf16_tc<128,1,1><<<grid, 256, SM128>>>(pH2BF, pWh2oBF, b_h2o, pLOGITBF, ROWS, DIN, HID);
    }
    // scores = logit @ W_out^T + b_out -> fp32 out
    {
        dim3 grid(VOCAB/256, ROWS/128);   // (125, 16)
        gemm_bf16_tc<256,0,0><<<grid, 256, SM256>>>(pLOGITBF, pWoutBF, b_out, out, ROWS, VOCAB, DIN);
    }

    softmax_rows<<<ROWS, 256>>>(out);
}